// round 5
// baseline (speedup 1.0000x reference)
#include <cuda_runtime.h>
#include <cuda_bf16.h>
#include <cstdint>

// TorchBSplineBasis: out[b, i*10+j] = A_b[i] * B_b[j], cubic B-spline bases
// (NUM_BASIS=10, DEGREE=3, 14 knots/dim) of t[b,0], t[b,1].
//
// R4 (resubmit; previous bench was a broker-capacity timeout):
// warp-autonomous double-buffered TMA store pipeline.
// Each warp owns 32-row tiles (12.8KB, contiguous in SMEM and gmem).
// compute(regs) -> STS -> lane0 cp.async.bulk + commit -> next tile.
// Double buffer per warp; wait_group.read 1 before buffer reuse, so the
// TMA drain of tile n overlaps the compute of tile n+1. No __syncthreads
// in the main loop; grid-stride over tiles; grid = 1 wave of 2 CTA/SM.

#define WARPS_PER_BLOCK 4
#define THREADS (WARPS_PER_BLOCK * 32)
#define TILE_ROWS 32
#define ROW_FLOATS 100
#define TILE_FLOATS (TILE_ROWS * ROW_FLOATS)          // 3200
#define NBUF 2
#define SMEM_BYTES (WARPS_PER_BLOCK * NBUF * TILE_FLOATS * 4)   // 102400

#define NB 10
#define NKNOT 14
#define NPAIRS 33           // 12 (k=1) + 11 (k=2) + 10 (k=3)

__device__ __forceinline__ uint32_t smem_u32(const void* p) {
    uint32_t a;
    asm("{ .reg .u64 t; cvta.to.shared.u64 t, %1; cvt.u32.u64 %0, t; }"
        : "=r"(a) : "l"(p));
    return a;
}

__global__ __launch_bounds__(THREADS)
void bspline_basis_kernel(const float* __restrict__ t,
                          const float* __restrict__ knots,
                          float* __restrict__ out,
                          int rows)
{
    extern __shared__ float s_prod[];   // [WARPS_PER_BLOCK][NBUF][TILE_FLOATS]
    __shared__ float s_kn[2][NKNOT];
    __shared__ float s_inv1[2][NPAIRS];
    __shared__ float s_inv2[2][NPAIRS];

    const int tid  = threadIdx.x;
    const int warp = tid >> 5;
    const int lane = tid & 31;

    if (tid < 2 * NKNOT) {
        s_kn[tid / NKNOT][tid % NKNOT] = knots[tid];
    }
    __syncthreads();

    // reciprocal tables, matching jnp.where(d==0, 0, 1/d)
    if (tid < 2 * NPAIRS) {
        int d = tid / NPAIRS;
        int p = tid % NPAIRS;
        int k, i;
        if (p < 12)      { k = 1; i = p; }
        else if (p < 23) { k = 2; i = p - 12; }
        else             { k = 3; i = p - 23; }
        float d1 = s_kn[d][i + k]     - s_kn[d][i];
        float d2 = s_kn[d][i + k + 1] - s_kn[d][i + 1];
        s_inv1[d][p] = (d1 == 0.0f) ? 0.0f : 1.0f / d1;
        s_inv2[d][p] = (d2 == 0.0f) ? 0.0f : 1.0f / d2;
    }
    __syncthreads();

    const int ntiles = (rows + TILE_ROWS - 1) / TILE_ROWS;
    const int gwarp  = blockIdx.x * WARPS_PER_BLOCK + warp;
    const int nwarps = gridDim.x * WARPS_PER_BLOCK;

    float* const mybufs = s_prod + warp * (NBUF * TILE_FLOATS);

    int it = 0;
    for (int tile = gwarp; tile < ntiles; tile += nwarps, it++) {
        const int row = tile * TILE_ROWS + lane;

        // ---- compute both bases into registers (no SMEM writes yet) ----
        float A[NB], Bb[NB];
        if (row < rows) {
            const float2 tv = *reinterpret_cast<const float2*>(t + (size_t)row * 2);
            const float tt[2] = { tv.x, tv.y };
            #pragma unroll
            for (int d = 0; d < 2; d++) {
                const float tc = tt[d];
                float Bv[13];
                #pragma unroll
                for (int i = 0; i < 13; i++) {
                    Bv[i] = (s_kn[d][i] <= tc && tc < s_kn[d][i + 1]) ? 1.0f : 0.0f;
                }
                int base = 0;
                #pragma unroll
                for (int k = 1; k <= 3; k++) {
                    const int m = 13 - k;
                    #pragma unroll
                    for (int i = 0; i < m; i++) {
                        float w1 = (tc - s_kn[d][i])         * s_inv1[d][base + i];
                        float w2 = (s_kn[d][i + k + 1] - tc) * s_inv2[d][base + i];
                        Bv[i] = w1 * Bv[i] + w2 * Bv[i + 1];
                    }
                    base += m;
                }
                float* dst = (d == 0) ? A : Bb;
                #pragma unroll
                for (int i = 0; i < NB; i++) dst[i] = Bv[i];
            }
        }

        float* const buf = mybufs + (it & 1) * TILE_FLOATS;

        // ---- ensure the group that last used this buffer has been read ----
        if (it >= NBUF) {
            if (lane == 0) {
                asm volatile("cp.async.bulk.wait_group.read 1;" ::: "memory");
            }
        }
        __syncwarp();

        // ---- outer product straight into gmem-layout SMEM (STS.128) ----
        if (row < rows) {
            float* dst = buf + lane * ROW_FLOATS;
            #pragma unroll
            for (int e = 0; e < ROW_FLOATS; e += 4) {
                float4 o;
                o.x = A[(e    ) / 10] * Bb[(e    ) % 10];
                o.y = A[(e + 1) / 10] * Bb[(e + 1) % 10];
                o.z = A[(e + 2) / 10] * Bb[(e + 2) % 10];
                o.w = A[(e + 3) / 10] * Bb[(e + 3) % 10];
                *reinterpret_cast<float4*>(dst + e) = o;
            }
        }
        __syncwarp();

        // ---- lane 0: async bulk store of this warp's contiguous tile ----
        if (lane == 0) {
            const int trows = min(TILE_ROWS, rows - tile * TILE_ROWS);
            const uint32_t bytes = (uint32_t)trows * (ROW_FLOATS * 4);
            const uint32_t saddr = smem_u32(buf);
            const uint64_t gaddr =
                (uint64_t)(uintptr_t)(out + (size_t)tile * TILE_ROWS * ROW_FLOATS);
            asm volatile("fence.proxy.async.shared::cta;" ::: "memory");
            asm volatile("cp.async.bulk.global.shared::cta.bulk_group [%0], [%1], %2;"
                         :: "l"(gaddr), "r"(saddr), "r"(bytes) : "memory");
            asm volatile("cp.async.bulk.commit_group;" ::: "memory");
        }
        __syncwarp();
    }

    // drain this warp's outstanding bulk reads before CTA teardown
    if (lane == 0) {
        asm volatile("cp.async.bulk.wait_group.read 0;" ::: "memory");
    }
}

extern "C" void kernel_launch(void* const* d_in, const int* in_sizes, int n_in,
                              void* d_out, int out_size) {
    const float* t     = (const float*)d_in[0];   // (BATCH, 2) fp32
    const float* knots = (const float*)d_in[1];   // (2, 14) fp32
    float* out = (float*)d_out;                   // (BATCH, 100) fp32

    const int rows = in_sizes[0] / 2;
    const int ntiles = (rows + TILE_ROWS - 1) / TILE_ROWS;

    // one wave at 2 CTA/SM on 148-SM GB300; shrink for tiny inputs
    int grid = 296;
    int needed = (ntiles + WARPS_PER_BLOCK - 1) / WARPS_PER_BLOCK;
    if (needed < grid) grid = needed;
    if (grid < 1) grid = 1;

    static bool attr_set = false;   // idempotent host-side attribute, not a work guard
    if (!attr_set) {
        cudaFuncSetAttribute(bspline_basis_kernel,
                             cudaFuncAttributeMaxDynamicSharedMemorySize,
                             SMEM_BYTES);
        attr_set = true;
    }

    bspline_basis_kernel<<<grid, THREADS, SMEM_BYTES>>>(t, knots, out, rows);
}

// round 6
// speedup vs baseline: 1.1160x; 1.1160x over previous
#include <cuda_runtime.h>
#include <cuda_bf16.h>
#include <cstdint>

// TorchBSplineBasis: out[b, i*10+j] = A_b[i] * B_b[j], cubic B-spline bases
// (NUM_BASIS=10, DEGREE=3, 14 knots/dim) of t[b,0], t[b,1].
//
// R6: sparse evaluation. Only 4 basis values per dim are nonzero (degree 3):
// find knot span j, run the Cox-de Boor DP on the 4-wide window (identical
// arithmetic to the dense DP), zero the SMEM row, scatter 16 products.
// Block structure = R3 (best so far): 128-thread CTA, gmem-layout SMEM tile,
// one cp.async.bulk per block; 4 CTAs/SM give cross-CTA compute/TMA overlap.

#define ROWS_PER_BLOCK 128
#define NB 10
#define NKNOT 14
#define NPAIRS 33           // 12 (k=1) + 11 (k=2) + 10 (k=3)
#define ROW_FLOATS 100
#define SMEM_PROD_BYTES (ROWS_PER_BLOCK * ROW_FLOATS * 4)   // 51200

__device__ __forceinline__ uint32_t smem_u32(const void* p) {
    uint32_t a;
    asm("{ .reg .u64 t; cvta.to.shared.u64 t, %1; cvt.u32.u64 %0, t; }"
        : "=r"(a) : "l"(p));
    return a;
}

__global__ __launch_bounds__(ROWS_PER_BLOCK)
void bspline_basis_kernel(const float* __restrict__ t,
                          const float* __restrict__ knots,
                          float* __restrict__ out,
                          int rows)
{
    extern __shared__ float s_prod[];          // [128][100], gmem layout
    __shared__ float s_kn[2][NKNOT];
    __shared__ float s_inv1[2][NPAIRS];
    __shared__ float s_inv2[2][NPAIRS];

    const int tid = threadIdx.x;

    if (tid < 2 * NKNOT) {
        s_kn[tid / NKNOT][tid % NKNOT] = knots[tid];
    }
    __syncthreads();

    // reciprocal tables, matching jnp.where(d==0, 0, 1/d)
    if (tid < 2 * NPAIRS) {
        int d = tid / NPAIRS;
        int p = tid % NPAIRS;
        int k, i;
        if (p < 12)      { k = 1; i = p; }
        else if (p < 23) { k = 2; i = p - 12; }
        else             { k = 3; i = p - 23; }
        float d1 = s_kn[d][i + k]     - s_kn[d][i];
        float d2 = s_kn[d][i + k + 1] - s_kn[d][i + 1];
        s_inv1[d][p] = (d1 == 0.0f) ? 0.0f : 1.0f / d1;
        s_inv2[d][p] = (d2 == 0.0f) ? 0.0f : 1.0f / d2;
    }
    __syncthreads();

    const int row0 = blockIdx.x * ROWS_PER_BLOCK;
    const int row  = row0 + tid;
    float* const dst = s_prod + tid * ROW_FLOATS;

    // zero this thread's SMEM row (25 independent STS.128)
    const float4 z4 = make_float4(0.f, 0.f, 0.f, 0.f);
    #pragma unroll
    for (int e = 0; e < ROW_FLOATS; e += 4) {
        *reinterpret_cast<float4*>(dst + e) = z4;
    }

    if (row < rows) {
        const float2 tv = *reinterpret_cast<const float2*>(t + (size_t)row * 2);
        const float tt[2] = { tv.x, tv.y };

        float vA[4], vB[4];
        int   jA = 0, jB = 0;

        #pragma unroll
        for (int d = 0; d < 2; d++) {
            const float tc = tt[d];

            // knot span: j = #{i in [1,13] : t >= kn[i]}  =>  kn[j] <= t < kn[j+1]
            int j = 0;
            #pragma unroll
            for (int i = 1; i < NKNOT; i++) j += (tc >= s_kn[d][i]) ? 1 : 0;
            const bool valid = (tc >= s_kn[d][0]) && (j < NKNOT - 1);

            // windowed Cox-de Boor: val[m] = B[j-k+m]^(k) for m = 0..k
            float val[4];
            val[0] = valid ? 1.0f : 0.0f;
            val[1] = val[2] = val[3] = 0.0f;

            int base = 0;
            #pragma unroll
            for (int k = 1; k <= 3; k++) {
                const int msz = 13 - k;            // table length at this level
                float nxt[4];
                #pragma unroll
                for (int m = 0; m <= k; m++) {
                    const int  i  = j - k + m;
                    const bool ok = ((unsigned)i < (unsigned)msz);
                    const int  ic = ok ? i : 0;
                    const float left  = (m > 0) ? val[m - 1] : 0.0f;
                    const float right = (m < k) ? val[m]     : 0.0f;
                    const float w1 = (tc - s_kn[d][ic])         * s_inv1[d][base + ic];
                    const float w2 = (s_kn[d][ic + k + 1] - tc) * s_inv2[d][base + ic];
                    nxt[m] = ok ? (w1 * left + w2 * right) : 0.0f;
                }
                #pragma unroll
                for (int m = 0; m <= k; m++) val[m] = nxt[m];
                base += msz;
            }

            if (d == 0) {
                jA = j;
                #pragma unroll
                for (int m = 0; m < 4; m++) vA[m] = val[m];
            } else {
                jB = j;
                #pragma unroll
                for (int m = 0; m < 4; m++) vB[m] = val[m];
            }
        }

        // scatter the 16 nonzero products: basis indices jA-3..jA x jB-3..jB
        #pragma unroll
        for (int a = 0; a < 4; a++) {
            const int ia = jA - 3 + a;
            if ((unsigned)ia < (unsigned)NB) {
                #pragma unroll
                for (int b = 0; b < 4; b++) {
                    const int ib = jB - 3 + b;
                    if ((unsigned)ib < (unsigned)NB) {
                        dst[ia * NB + ib] = vA[a] * vB[b];
                    }
                }
            }
        }
    }
    __syncthreads();

    // one TMA bulk store: SMEM image is byte-identical to the gmem destination
    if (tid == 0) {
        const int tileRows = min(ROWS_PER_BLOCK, rows - row0);
        const uint32_t bytes = (uint32_t)tileRows * (ROW_FLOATS * 4);
        const uint32_t saddr = smem_u32(s_prod);
        const uint64_t gaddr = (uint64_t)(uintptr_t)(out + (size_t)row0 * ROW_FLOATS);

        asm volatile("fence.proxy.async.shared::cta;" ::: "memory");
        asm volatile("cp.async.bulk.global.shared::cta.bulk_group [%0], [%1], %2;"
                     :: "l"(gaddr), "r"(saddr), "r"(bytes) : "memory");
        asm volatile("cp.async.bulk.commit_group;" ::: "memory");
        asm volatile("cp.async.bulk.wait_group.read 0;" ::: "memory");
    }
}

extern "C" void kernel_launch(void* const* d_in, const int* in_sizes, int n_in,
                              void* d_out, int out_size) {
    const float* t     = (const float*)d_in[0];   // (BATCH, 2) fp32
    const float* knots = (const float*)d_in[1];   // (2, 14) fp32
    float* out = (float*)d_out;                   // (BATCH, 100) fp32

    const int rows = in_sizes[0] / 2;
    const int grid = (rows + ROWS_PER_BLOCK - 1) / ROWS_PER_BLOCK;

    static bool attr_set = false;   // idempotent host-side attribute, not a work guard
    if (!attr_set) {
        cudaFuncSetAttribute(bspline_basis_kernel,
                             cudaFuncAttributeMaxDynamicSharedMemorySize,
                             SMEM_PROD_BYTES);
        attr_set = true;
    }

    bspline_basis_kernel<<<grid, ROWS_PER_BLOCK, SMEM_PROD_BYTES>>>(t, knots, out, rows);
}